// round 6
// baseline (speedup 1.0000x reference)
#include <cuda_runtime.h>
#include <cstdint>

#define NN 100000
#define NE 400000
#define D  128
#define BN_EPS 1e-5f

// ---------------- scratch (static device globals; no allocation) ------------
__device__ float g_h [(size_t)NN * D];   // feature + scatter-sum  (GEMM1 input)
__device__ float g_h1[(size_t)NN * D];   // relu(h@w1^T+b1)        (GEMM2 input)
__device__ float g_wt1[D * D];           // w1 transposed: wt1[k*D+j] = w1[j*D+k]
__device__ float g_wt2[D * D];
__device__ float g_sum[D];
__device__ float g_sq [D];
__device__ float g_scale[D];
__device__ float g_shift[D];
__device__ int   g_is64;

// ---------------- edge-index dtype detection --------------------------------
// int64 edges: every 8-byte value is in [0, NN). int32 edges reinterpreted as
// u64 pack two edges: value = lo + hi*2^32 >= 2^32 unless hi == 0 (prob 1e-5
// per element; all-64 passing is ~impossible). Deterministic per input.
__global__ void k_detect(const unsigned long long* __restrict__ ei) {
    if (threadIdx.x == 0) {
        int ok = 1;
        for (int i = 0; i < 64; i++)
            if (ei[i] >= (unsigned long long)NN) { ok = 0; break; }
        g_is64 = ok;
    }
}

// ---------------- init: h = feature, zero BN accumulators -------------------
__global__ void k_init(const float4* __restrict__ feat) {
    int stride = gridDim.x * blockDim.x;
    float4* dst = reinterpret_cast<float4*>(g_h);
    for (int i = blockIdx.x * blockDim.x + threadIdx.x; i < NN * D / 4; i += stride)
        dst[i] = feat[i];
    if (blockIdx.x == 0 && threadIdx.x < D) {
        g_sum[threadIdx.x] = 0.f;
        g_sq [threadIdx.x] = 0.f;
    }
}

// ---------------- transpose weights (tiny, 2*16K elements) ------------------
__global__ void k_transpose(const float* __restrict__ w1, const float* __restrict__ w2) {
    int idx = blockIdx.x * blockDim.x + threadIdx.x;
    if (idx < D * D) {
        g_wt1[idx] = w1[(idx % D) * D + idx / D];
    } else if (idx < 2 * D * D) {
        int t = idx - D * D;
        g_wt2[t] = w2[(t % D) * D + t / D];
    }
}

// ---------------- edge scatter: h[dst] += feature[src] ----------------------
// One warp per edge; lane l handles float4 element l of the 128-float row.
__global__ void k_edge(const void* __restrict__ ei, const float* __restrict__ feat) {
    int gw   = (blockIdx.x * blockDim.x + threadIdx.x) >> 5;
    int lane = threadIdx.x & 31;
    if (gw >= NE) return;

    int src, dst;
    if (g_is64) {
        const long long* p = reinterpret_cast<const long long*>(ei);
        src = (int)p[gw];
        dst = (int)p[NE + gw];
    } else {
        const int* p = reinterpret_cast<const int*>(ei);
        src = p[gw];
        dst = p[NE + gw];
    }

    float4 v = reinterpret_cast<const float4*>(feat + (size_t)src * D)[lane];
    float* o = g_h + (size_t)dst * D + lane * 4;
    asm volatile("red.global.add.v4.f32 [%0], {%1,%2,%3,%4};"
                 :: "l"(o), "f"(v.x), "f"(v.y), "f"(v.z), "f"(v.w)
                 : "memory");
}

// ---------------- fused GEMM + bias + ReLU (+ BN stats for layer 2) ---------
// C[i][j] = relu( sum_k A[i][k]*Wt[k][j] + bias[j] )
// BM=64, BN=128 (full), BK=32, 256 threads, 4x8 microtile per thread.
template <int LAYER>
__global__ __launch_bounds__(256)
void k_gemm(const float* __restrict__ bias, float* __restrict__ Cout) {
    const float* __restrict__ A  = (LAYER == 1) ? g_h   : g_h1;
    const float* __restrict__ Bt = (LAYER == 1) ? g_wt1 : g_wt2;
    float* __restrict__ C        = (LAYER == 1) ? g_h1  : Cout;
    constexpr bool STATS = (LAYER == 2);

    __shared__ float As[64][36];        // pad 36: conflict-free, float4-aligned rows
    __shared__ float Bs[32][128];
    __shared__ float s_sum[D];
    __shared__ float s_sq [D];

    const int tid  = threadIdx.x;
    const int tx   = tid & 15;          // column group
    const int ty   = tid >> 4;          // row group
    const int tx4  = tx * 4;
    const int ty4  = ty * 4;
    const int row0 = blockIdx.x * 64;

    float acc[4][8];
    #pragma unroll
    for (int i = 0; i < 4; i++)
        #pragma unroll
        for (int j = 0; j < 8; j++) acc[i][j] = 0.f;

    #pragma unroll 1
    for (int kk = 0; kk < 4; kk++) {
        // --- load A tile: 64x32 floats = 512 float4, 2 per thread ---
        #pragma unroll
        for (int i = 0; i < 2; i++) {
            int g  = tid + i * 256;
            int r  = g >> 3;            // 0..63
            int c4 = g & 7;             // 0..7
            float4 v = make_float4(0.f, 0.f, 0.f, 0.f);
            int gr = row0 + r;
            if (gr < NN)
                v = *reinterpret_cast<const float4*>(A + (size_t)gr * D + kk * 32 + c4 * 4);
            *reinterpret_cast<float4*>(&As[r][c4 * 4]) = v;
        }
        // --- load B tile: 32x128 floats = 1024 float4, 4 per thread ---
        #pragma unroll
        for (int i = 0; i < 4; i++) {
            int g  = tid + i * 256;
            int r  = g >> 5;            // 0..31
            int c4 = g & 31;            // 0..31
            *reinterpret_cast<float4*>(&Bs[r][c4 * 4]) =
                *reinterpret_cast<const float4*>(Bt + (size_t)(kk * 32 + r) * D + c4 * 4);
        }
        __syncthreads();

        #pragma unroll
        for (int k = 0; k < 32; k++) {
            float a0 = As[ty4 + 0][k];
            float a1 = As[ty4 + 1][k];
            float a2 = As[ty4 + 2][k];
            float a3 = As[ty4 + 3][k];
            float4 b0 = *reinterpret_cast<float4*>(&Bs[k][tx4]);
            float4 b1 = *reinterpret_cast<float4*>(&Bs[k][64 + tx4]);

            acc[0][0] = fmaf(a0, b0.x, acc[0][0]);
            acc[0][1] = fmaf(a0, b0.y, acc[0][1]);
            acc[0][2] = fmaf(a0, b0.z, acc[0][2]);
            acc[0][3] = fmaf(a0, b0.w, acc[0][3]);
            acc[0][4] = fmaf(a0, b1.x, acc[0][4]);
            acc[0][5] = fmaf(a0, b1.y, acc[0][5]);
            acc[0][6] = fmaf(a0, b1.z, acc[0][6]);
            acc[0][7] = fmaf(a0, b1.w, acc[0][7]);

            acc[1][0] = fmaf(a1, b0.x, acc[1][0]);
            acc[1][1] = fmaf(a1, b0.y, acc[1][1]);
            acc[1][2] = fmaf(a1, b0.z, acc[1][2]);
            acc[1][3] = fmaf(a1, b0.w, acc[1][3]);
            acc[1][4] = fmaf(a1, b1.x, acc[1][4]);
            acc[1][5] = fmaf(a1, b1.y, acc[1][5]);
            acc[1][6] = fmaf(a1, b1.z, acc[1][6]);
            acc[1][7] = fmaf(a1, b1.w, acc[1][7]);

            acc[2][0] = fmaf(a2, b0.x, acc[2][0]);
            acc[2][1] = fmaf(a2, b0.y, acc[2][1]);
            acc[2][2] = fmaf(a2, b0.z, acc[2][2]);
            acc[2][3] = fmaf(a2, b0.w, acc[2][3]);
            acc[2][4] = fmaf(a2, b1.x, acc[2][4]);
            acc[2][5] = fmaf(a2, b1.y, acc[2][5]);
            acc[2][6] = fmaf(a2, b1.z, acc[2][6]);
            acc[2][7] = fmaf(a2, b1.w, acc[2][7]);

            acc[3][0] = fmaf(a3, b0.x, acc[3][0]);
            acc[3][1] = fmaf(a3, b0.y, acc[3][1]);
            acc[3][2] = fmaf(a3, b0.z, acc[3][2]);
            acc[3][3] = fmaf(a3, b0.w, acc[3][3]);
            acc[3][4] = fmaf(a3, b1.x, acc[3][4]);
            acc[3][5] = fmaf(a3, b1.y, acc[3][5]);
            acc[3][6] = fmaf(a3, b1.z, acc[3][6]);
            acc[3][7] = fmaf(a3, b1.w, acc[3][7]);
        }
        __syncthreads();
    }

    // ---------------- epilogue: bias + relu + store (+ stats) ---------------
    float4 bi0 = *reinterpret_cast<const float4*>(&bias[tx4]);
    float4 bi1 = *reinterpret_cast<const float4*>(&bias[64 + tx4]);

    float s[8], q[8];
    #pragma unroll
    for (int j = 0; j < 8; j++) { s[j] = 0.f; q[j] = 0.f; }

    #pragma unroll
    for (int i = 0; i < 4; i++) {
        int r = row0 + ty4 + i;
        if (r < NN) {
            float4 v0, v1;
            v0.x = fmaxf(acc[i][0] + bi0.x, 0.f);
            v0.y = fmaxf(acc[i][1] + bi0.y, 0.f);
            v0.z = fmaxf(acc[i][2] + bi0.z, 0.f);
            v0.w = fmaxf(acc[i][3] + bi0.w, 0.f);
            v1.x = fmaxf(acc[i][4] + bi1.x, 0.f);
            v1.y = fmaxf(acc[i][5] + bi1.y, 0.f);
            v1.z = fmaxf(acc[i][6] + bi1.z, 0.f);
            v1.w = fmaxf(acc[i][7] + bi1.w, 0.f);
            *reinterpret_cast<float4*>(&C[(size_t)r * D + tx4])      = v0;
            *reinterpret_cast<float4*>(&C[(size_t)r * D + 64 + tx4]) = v1;
            if (STATS) {
                s[0] += v0.x; q[0] += v0.x * v0.x;
                s[1] += v0.y; q[1] += v0.y * v0.y;
                s[2] += v0.z; q[2] += v0.z * v0.z;
                s[3] += v0.w; q[3] += v0.w * v0.w;
                s[4] += v1.x; q[4] += v1.x * v1.x;
                s[5] += v1.y; q[5] += v1.y * v1.y;
                s[6] += v1.z; q[6] += v1.z * v1.z;
                s[7] += v1.w; q[7] += v1.w * v1.w;
            }
        }
    }

    if (STATS) {
        if (tid < D) { s_sum[tid] = 0.f; s_sq[tid] = 0.f; }
        __syncthreads();
        #pragma unroll
        for (int j = 0; j < 4; j++) {
            atomicAdd(&s_sum[tx4 + j],      s[j]);
            atomicAdd(&s_sq [tx4 + j],      q[j]);
            atomicAdd(&s_sum[64 + tx4 + j], s[4 + j]);
            atomicAdd(&s_sq [64 + tx4 + j], q[4 + j]);
        }
        __syncthreads();
        if (tid < D) {
            atomicAdd(&g_sum[tid], s_sum[tid]);
            atomicAdd(&g_sq [tid], s_sq [tid]);
        }
    }
}

// ---------------- BN finalize: per-column scale/shift ----------------------
__global__ void k_finalize(const float* __restrict__ gamma, const float* __restrict__ beta) {
    int j = threadIdx.x;
    float inv_n = 1.0f / (float)NN;
    float mean  = g_sum[j] * inv_n;
    float var   = g_sq[j] * inv_n - mean * mean;
    float sc    = gamma[j] * rsqrtf(var + BN_EPS);
    g_scale[j]  = sc;
    g_shift[j]  = beta[j] - mean * sc;
}

// ---------------- BN apply in place on d_out --------------------------------
__global__ void k_norm(float4* __restrict__ out) {
    __shared__ float sc[D], sh[D];
    if (threadIdx.x < D) {
        sc[threadIdx.x] = g_scale[threadIdx.x];
        sh[threadIdx.x] = g_shift[threadIdx.x];
    }
    __syncthreads();
    int stride = gridDim.x * blockDim.x;
    for (int i = blockIdx.x * blockDim.x + threadIdx.x; i < NN * D / 4; i += stride) {
        int c = (i & 31) * 4;           // (i*4) % 128
        float4 v = out[i];
        v.x = fmaf(v.x, sc[c + 0], sh[c + 0]);
        v.y = fmaf(v.y, sc[c + 1], sh[c + 1]);
        v.z = fmaf(v.z, sc[c + 2], sh[c + 2]);
        v.w = fmaf(v.w, sc[c + 3], sh[c + 3]);
        out[i] = v;
    }
}

// ---------------- launch -----------------------------------------------------
extern "C" void kernel_launch(void* const* d_in, const int* in_sizes, int n_in,
                              void* d_out, int out_size) {
    const float* feat  = (const float*)d_in[0];
    const void*  ei    = d_in[1];
    const float* w1    = (const float*)d_in[2];
    const float* b1    = (const float*)d_in[3];
    const float* w2    = (const float*)d_in[4];
    const float* b2    = (const float*)d_in[5];
    const float* gamma = (const float*)d_in[6];
    const float* beta  = (const float*)d_in[7];
    float* out = (float*)d_out;
    (void)in_sizes; (void)n_in; (void)out_size;

    k_detect<<<1, 32>>>((const unsigned long long*)ei);
    k_init<<<1184, 256>>>((const float4*)feat);
    k_transpose<<<(2 * D * D + 255) / 256, 256>>>(w1, w2);
    k_edge<<<NE / 8, 256>>>(ei, feat);                 // 8 warps/block, 1 edge/warp
    k_gemm<1><<<(NN + 63) / 64, 256>>>(b1, out);       // writes g_h1 (out unused)
    k_gemm<2><<<(NN + 63) / 64, 256>>>(b2, out);       // writes out + BN stats
    k_finalize<<<1, D>>>(gamma, beta);
    k_norm<<<1184, 256>>>((float4*)out);
}